// round 2
// baseline (speedup 1.0000x reference)
#include <cuda_runtime.h>
#include <cstdint>

// Problem constants (fixed by the reference: SHAPE = (8192, 4096), P = 0.3)
#define N_ELEMS   (8192 * 4096)        // 33,554,432 floats
#define N_WORDS   (N_ELEMS / 32)       // 1,048,576 uint32 mask words = 4 MB
#define N_FLOAT4  (N_ELEMS / 4)        // 8,388,608 float4s

// Scratch: 1 bit per element. Lives in L2 during the hot phase.
__device__ uint32_t g_mask[N_WORDS];

// ---------------------------------------------------------------------------
// Kernel 1: clear the bitmask (runs every launch; graph replays reuse it).
// ---------------------------------------------------------------------------
__global__ void clear_mask_kernel() {
    int i = blockIdx.x * blockDim.x + threadIdx.x;  // 0 .. N_WORDS/4 - 1
    reinterpret_cast<uint4*>(g_mask)[i] = make_uint4(0u, 0u, 0u, 0u);
}

// ---------------------------------------------------------------------------
// Kernel 2: scatter-set bits from the int32 index list.
// Each thread consumes 4 indices via one 16B load; tail handled by thread 0.
// atomicOr with unused return compiles to RED.OR (no round trip).
// ---------------------------------------------------------------------------
__global__ void set_bits_kernel(const int* __restrict__ idx, int n_quads,
                                int k) {
    int i = blockIdx.x * blockDim.x + threadIdx.x;
    if (i < n_quads) {
        int4 v = reinterpret_cast<const int4*>(idx)[i];
        unsigned int a = (unsigned int)v.x;
        unsigned int b = (unsigned int)v.y;
        unsigned int c = (unsigned int)v.z;
        unsigned int d = (unsigned int)v.w;
        atomicOr(&g_mask[a >> 5], 1u << (a & 31));
        atomicOr(&g_mask[b >> 5], 1u << (b & 31));
        atomicOr(&g_mask[c >> 5], 1u << (c & 31));
        atomicOr(&g_mask[d >> 5], 1u << (d & 31));
    }
    if (i == 0) {
        for (int j = n_quads * 4; j < k; j++) {
            unsigned int a = (unsigned int)idx[j];
            atomicOr(&g_mask[a >> 5], 1u << (a & 31));
        }
    }
}

// ---------------------------------------------------------------------------
// Kernel 3: fused copy + masked zero.
// Thread handles one float4; 8 consecutive threads share one mask word
// (L1 broadcast). Streaming read of X, streaming write of out.
// ---------------------------------------------------------------------------
__global__ void apply_mask_kernel(const float4* __restrict__ X,
                                  float4* __restrict__ out) {
    int i = blockIdx.x * blockDim.x + threadIdx.x;  // float4 index
    float4 v = X[i];
    uint32_t w = g_mask[i >> 3];
    uint32_t nib = w >> ((i & 7) * 4);
    if (nib & 1u) v.x = 0.0f;
    if (nib & 2u) v.y = 0.0f;
    if (nib & 4u) v.z = 0.0f;
    if (nib & 8u) v.w = 0.0f;
    out[i] = v;
}

extern "C" void kernel_launch(void* const* d_in, const int* in_sizes, int n_in,
                              void* d_out, int out_size) {
    const float* X = (const float*)d_in[0];
    const int* drop_idx = (const int*)d_in[1];   // JAX default x64-disabled => int32
    int k = in_sizes[1];                          // number of indices
    float* out = (float*)d_out;

    // 1) clear mask
    {
        int threads = 256;
        int total = N_WORDS / 4;       // uint4 stores
        clear_mask_kernel<<<total / threads, threads>>>();
    }

    // 2) scatter bits
    {
        int n_quads = k / 4;
        int threads = 256;
        int blocks = (n_quads + threads - 1) / threads;
        set_bits_kernel<<<blocks, threads>>>(drop_idx, n_quads, k);
    }

    // 3) fused copy + zero
    {
        int threads = 256;
        int blocks = N_FLOAT4 / threads;  // 32768
        apply_mask_kernel<<<blocks, threads>>>((const float4*)X, (float4*)out);
    }
}

// round 3
// speedup vs baseline: 1.0003x; 1.0003x over previous
#include <cuda_runtime.h>
#include <cstdint>

// Problem constants (fixed by the reference: SHAPE = (8192, 4096), P = 0.3)
#define N_ELEMS   (8192 * 4096)        // 33,554,432 floats
#define N_WORDS   (N_ELEMS / 32)       // 1,048,576 uint32 mask words = 4 MB
#define N_FLOAT4  (N_ELEMS / 4)        // 8,388,608 float4s

// Scratch: 1 bit per element. Zero-initialized at module load; every apply
// pass re-zeroes it for the next graph replay (self-cleaning).
__device__ uint32_t g_mask[N_WORDS];

// ---------------------------------------------------------------------------
// Kernel 1: scatter-set bits from the int32 index list.
// Grid-stride; each iteration consumes 4 indices via one 16B streaming load.
// atomicOr with unused return compiles to RED.OR (no round trip).
// idx loaded with .cs so it doesn't evict the mask from L2.
// ---------------------------------------------------------------------------
__global__ void set_bits_kernel(const int4* __restrict__ idx4, int n_quads,
                                const int* __restrict__ idx, int k) {
    int stride = gridDim.x * blockDim.x;
    for (int i = blockIdx.x * blockDim.x + threadIdx.x; i < n_quads; i += stride) {
        int4 v = __ldcs(&idx4[i]);
        unsigned int a = (unsigned int)v.x;
        unsigned int b = (unsigned int)v.y;
        unsigned int c = (unsigned int)v.z;
        unsigned int d = (unsigned int)v.w;
        atomicOr(&g_mask[a >> 5], 1u << (a & 31));
        atomicOr(&g_mask[b >> 5], 1u << (b & 31));
        atomicOr(&g_mask[c >> 5], 1u << (c & 31));
        atomicOr(&g_mask[d >> 5], 1u << (d & 31));
    }
    // tail (k % 4 != 0)
    if (blockIdx.x == 0 && threadIdx.x == 0) {
        for (int j = n_quads * 4; j < k; j++) {
            unsigned int a = (unsigned int)idx[j];
            atomicOr(&g_mask[a >> 5], 1u << (a & 31));
        }
    }
}

// ---------------------------------------------------------------------------
// Kernel 2: fused copy + masked zero + mask self-clean.
// Thread handles one float4; 8 consecutive threads (same warp) share one mask
// word. Lane (i&7)==0 zeroes the word AFTER the group's loads (warp program
// order guarantees the LDG instruction precedes the STG for all lanes).
// X read .cs (evict-first), out written .cs — keeps the mask L2-resident.
// ---------------------------------------------------------------------------
__global__ void apply_mask_kernel(const float4* __restrict__ X,
                                  float4* __restrict__ out) {
    int i = blockIdx.x * blockDim.x + threadIdx.x;  // float4 index
    uint32_t w = g_mask[i >> 3];
    float4 v = __ldcs(&X[i]);
    uint32_t nib = w >> ((i & 7) * 4);
    if (nib & 1u) v.x = 0.0f;
    if (nib & 2u) v.y = 0.0f;
    if (nib & 4u) v.z = 0.0f;
    if (nib & 8u) v.w = 0.0f;
    __stcs(&out[i], v);
    if ((i & 7) == 0) g_mask[i >> 3] = 0u;   // self-clean for next replay
}

extern "C" void kernel_launch(void* const* d_in, const int* in_sizes, int n_in,
                              void* d_out, int out_size) {
    const float* X = (const float*)d_in[0];
    const int* drop_idx = (const int*)d_in[1];   // JAX x64-disabled => int32
    int k = in_sizes[1];                          // number of indices
    float* out = (float*)d_out;

    // 1) scatter bits (mask is guaranteed zero: module init or previous apply)
    {
        int n_quads = k / 4;
        int threads = 256;
        int blocks = 2368;             // 16 * 148 SMs, grid-stride saturating
        set_bits_kernel<<<blocks, threads>>>((const int4*)drop_idx, n_quads,
                                             drop_idx, k);
    }

    // 2) fused copy + zero + mask clear
    {
        int threads = 256;
        int blocks = N_FLOAT4 / threads;  // 32768
        apply_mask_kernel<<<blocks, threads>>>((const float4*)X, (float4*)out);
    }
}